// round 2
// baseline (speedup 1.0000x reference)
#include <cuda_runtime.h>
#include <math.h>
#include <stdint.h>
#include <stddef.h>

#define N_ENT 50000
#define N_TX  40000
#define D     128
#define F     432
#define T     11
#define CDIM  (F + T * D)      /* 1840 */
#define QLD   512              /* q|k|v|out packed per entity row */
#define EPS   1e-5f
#define SCALE 0.08838834764831845f  /* 1/sqrt(128) */

/* ------------------------------------------------------------------ */
/* Scratch (allocation-free: __device__ globals)                       */
/* ------------------------------------------------------------------ */
__device__ float    g_qkvs[(size_t)N_ENT * QLD];    /* 102.4 MB: q|k|v|attn-out */
__device__ float    g_hn[(size_t)N_ENT * D];        /* 25.6 MB LayerNorm output */
__device__ float    g_scores[N_TX];
__device__ float    g_ex[N_TX];
__device__ float    g_denom[N_ENT];
__device__ unsigned g_m[N_ENT];
__device__ float    g_comb[(size_t)N_TX * CDIM];    /* 294 MB combined features */
__device__ float    g_x1[(size_t)N_TX * D];
__device__ float    g_x2[(size_t)N_TX * 64];
__device__ float    g_Bcat[D * QLD];                /* [Wq|Wk|Wv|Ws] packed */
__device__ float    g_bcat[QLD];

/* ------------------------------------------------------------------ */
/* Helpers: order-preserving float<->uint encoding for atomicMax      */
/* ------------------------------------------------------------------ */
__device__ __forceinline__ unsigned f2o(float f) {
    unsigned u = __float_as_uint(f);
    return (u & 0x80000000u) ? ~u : (u | 0x80000000u);
}
__device__ __forceinline__ float o2f(unsigned u) {
    return (u & 0x80000000u) ? __uint_as_float(u & 0x7FFFFFFFu)
                             : __uint_as_float(~u);
}

/* ------------------------------------------------------------------ */
/* Pack [Wq|Wk|Wv|Ws] -> Bcat [128 x 512], biases -> bcat[512]         */
/* ------------------------------------------------------------------ */
__global__ void pack_w(const float* __restrict__ Wq, const float* __restrict__ Wk,
                       const float* __restrict__ Wv, const float* __restrict__ Ws,
                       const float* __restrict__ bq, const float* __restrict__ bk,
                       const float* __restrict__ bv, const float* __restrict__ bs,
                       float* __restrict__ Bcat, float* __restrict__ bcat) {
    int i = blockIdx.x * blockDim.x + threadIdx.x;   /* 0 .. 65535 */
    if (i >= D * QLD) return;
    int n = i & (QLD - 1);
    int k = i >> 9;
    const float* W = (n < 128) ? Wq : (n < 256) ? Wk : (n < 384) ? Wv : Ws;
    int nn = n & 127;
    Bcat[k * QLD + n] = W[k * 128 + nn];
    if (k == 0) {
        const float* bb = (n < 128) ? bq : (n < 256) ? bk : (n < 384) ? bv : bs;
        bcat[n] = bb[nn];
    }
}

/* ------------------------------------------------------------------ */
/* combined[:, :432] = tx_x ; combined[:, 432:] = 0                    */
/* ------------------------------------------------------------------ */
__global__ void comb_init(const float* __restrict__ tx, float* __restrict__ comb) {
    int i = blockIdx.x * blockDim.x + threadIdx.x;    /* one float4 each */
    const int TOT = N_TX * (CDIM / 4);                /* 18.4M */
    if (i >= TOT) return;
    int row = i / (CDIM / 4);
    int c4  = i - row * (CDIM / 4);
    float4 v = make_float4(0.f, 0.f, 0.f, 0.f);
    if (c4 < F / 4) v = ((const float4*)(tx + (size_t)row * F))[c4];
    ((float4*)(comb + (size_t)row * CDIM))[c4] = v;
}

__global__ void init_md(unsigned* __restrict__ m, float* __restrict__ denom) {
    int i = blockIdx.x * blockDim.x + threadIdx.x;
    if (i < N_ENT) { m[i] = 0u; denom[i] = 0.f; }
}

/* ------------------------------------------------------------------ */
/* SGEMM: C[M,N] = gatherA[M,K] @ B[K,N] + bias (opt relu)             */
/* BM=BN=64, BK=16, 256 threads, 4x4 per thread. K%16==0, N%64==0.     */
/* ------------------------------------------------------------------ */
__global__ void __launch_bounds__(256) sgemm64(
    const float* __restrict__ A, const int* __restrict__ rowidx,
    const float* __restrict__ B, const float* __restrict__ bias,
    float* __restrict__ C, int M, int N, int K, int relu) {
    __shared__ float As[16][64];
    __shared__ float Bs[16][64];
    const int tid = threadIdx.x;
    const int tx = tid & 15;
    const int ty = tid >> 4;
    const int m0 = blockIdx.y * 64;
    const int n0 = blockIdx.x * 64;

    const int lrow = tid >> 2;   /* 0..63 */
    const int lcg  = tid & 3;    /* 0..3  */
    const int gm = m0 + lrow;
    const float* arow = NULL;
    if (gm < M) {
        int r = rowidx ? rowidx[gm] : gm;
        arow = A + (size_t)r * K;
    }
    const int brow = tid >> 4;   /* 0..15 */
    const int bcg  = tid & 15;   /* 0..15 */

    float acc[4][4];
#pragma unroll
    for (int i = 0; i < 4; i++)
#pragma unroll
        for (int j = 0; j < 4; j++) acc[i][j] = 0.f;

    for (int k0 = 0; k0 < K; k0 += 16) {
        float4 av = make_float4(0.f, 0.f, 0.f, 0.f);
        if (arow) av = *(const float4*)(arow + k0 + (lcg << 2));
        As[(lcg << 2) + 0][lrow] = av.x;
        As[(lcg << 2) + 1][lrow] = av.y;
        As[(lcg << 2) + 2][lrow] = av.z;
        As[(lcg << 2) + 3][lrow] = av.w;
        float4 bv = *(const float4*)(B + (size_t)(k0 + brow) * N + n0 + (bcg << 2));
        *(float4*)(&Bs[brow][bcg << 2]) = bv;
        __syncthreads();
#pragma unroll
        for (int kk = 0; kk < 16; kk++) {
            float4 a = *(const float4*)(&As[kk][ty << 2]);
            float4 b = *(const float4*)(&Bs[kk][tx << 2]);
            acc[0][0] += a.x * b.x; acc[0][1] += a.x * b.y; acc[0][2] += a.x * b.z; acc[0][3] += a.x * b.w;
            acc[1][0] += a.y * b.x; acc[1][1] += a.y * b.y; acc[1][2] += a.y * b.z; acc[1][3] += a.y * b.w;
            acc[2][0] += a.z * b.x; acc[2][1] += a.z * b.y; acc[2][2] += a.z * b.z; acc[2][3] += a.z * b.w;
            acc[3][0] += a.w * b.x; acc[3][1] += a.w * b.y; acc[3][2] += a.w * b.z; acc[3][3] += a.w * b.w;
        }
        __syncthreads();
    }
    const int nbase = n0 + (tx << 2);
    float4 bb = *(const float4*)(bias + nbase);
#pragma unroll
    for (int i = 0; i < 4; i++) {
        int m = m0 + (ty << 2) + i;
        if (m >= M) continue;
        float4 o;
        o.x = acc[i][0] + bb.x;
        o.y = acc[i][1] + bb.y;
        o.z = acc[i][2] + bb.z;
        o.w = acc[i][3] + bb.w;
        if (relu) {
            o.x = fmaxf(o.x, 0.f); o.y = fmaxf(o.y, 0.f);
            o.z = fmaxf(o.z, 0.f); o.w = fmaxf(o.w, 0.f);
        }
        *(float4*)(C + (size_t)m * N + nbase) = o;
    }
}

/* ------------------------------------------------------------------ */
/* Edge pass 1: scores[e] = dot(q[dst], k[src]) * scale; seg atomicMax */
/* warp per edge                                                       */
/* ------------------------------------------------------------------ */
__global__ void edge_scores(const float* __restrict__ qkvs,
                            const int* __restrict__ src, const int* __restrict__ dst,
                            float* __restrict__ scores, unsigned* __restrict__ mEnc) {
    int e = (blockIdx.x * blockDim.x + threadIdx.x) >> 5;
    int lane = threadIdx.x & 31;
    if (e >= N_TX) return;
    int dd = dst[e], ss = src[e];
    float4 qv = ((const float4*)(qkvs + (size_t)dd * QLD))[lane];
    float4 kv = ((const float4*)(qkvs + (size_t)ss * QLD + 128))[lane];
    float acc = qv.x * kv.x + qv.y * kv.y + qv.z * kv.z + qv.w * kv.w;
#pragma unroll
    for (int o = 16; o; o >>= 1) acc += __shfl_xor_sync(0xFFFFFFFFu, acc, o);
    acc *= SCALE;
    if (lane == 0) {
        scores[e] = acc;
        atomicMax(&mEnc[dd], f2o(acc));
    }
}

/* Edge pass 2: ex = exp(score - m[dst]); denom[dst] += ex             */
__global__ void edge_exp(const float* __restrict__ scores, const int* __restrict__ dst,
                         const unsigned* __restrict__ mEnc,
                         float* __restrict__ ex, float* __restrict__ denom) {
    int e = blockIdx.x * blockDim.x + threadIdx.x;
    if (e >= N_TX) return;
    int dd = dst[e];
    float v = expf(scores[e] - o2f(mEnc[dd]));
    ex[e] = v;
    atomicAdd(&denom[dd], v);
}

/* Edge pass 3: out[dst] += (ex/denom[dst]) * v[src]  (warp per edge)  */
__global__ void edge_agg(const float* __restrict__ ex, const float* __restrict__ denom,
                         const int* __restrict__ src, const int* __restrict__ dst,
                         float* __restrict__ qkvs) {
    int e = (blockIdx.x * blockDim.x + threadIdx.x) >> 5;
    int lane = threadIdx.x & 31;
    if (e >= N_TX) return;
    int dd = dst[e], ss = src[e];
    float alpha = ex[e] / denom[dd];
    float4 vv = ((const float4*)(qkvs + (size_t)ss * QLD + 256))[lane];
    float* o = qkvs + (size_t)dd * QLD + 384 + (lane << 2);
    atomicAdd(o + 0, alpha * vv.x);
    atomicAdd(o + 1, alpha * vv.y);
    atomicAdd(o + 2, alpha * vv.z);
    atomicAdd(o + 3, alpha * vv.w);
}

/* LayerNorm on the attn-out slice (col 384..511), warp per row        */
__global__ void layernorm(const float* __restrict__ qkvs,
                          const float* __restrict__ g, const float* __restrict__ b,
                          float* __restrict__ hn) {
    int r = (blockIdx.x * blockDim.x + threadIdx.x) >> 5;
    int lane = threadIdx.x & 31;
    if (r >= N_ENT) return;
    float4 x = ((const float4*)(qkvs + (size_t)r * QLD + 384))[lane];
    float s = x.x + x.y + x.z + x.w;
#pragma unroll
    for (int o = 16; o; o >>= 1) s += __shfl_xor_sync(0xFFFFFFFFu, s, o);
    float mu = s * (1.f / 128.f);
    float dx = x.x - mu, dy = x.y - mu, dz = x.z - mu, dw = x.w - mu;
    float v = dx * dx + dy * dy + dz * dz + dw * dw;
#pragma unroll
    for (int o = 16; o; o >>= 1) v += __shfl_xor_sync(0xFFFFFFFFu, v, o);
    float rstd = rsqrtf(v * (1.f / 128.f) + EPS);
    float4 gg = ((const float4*)g)[lane];
    float4 bb = ((const float4*)b)[lane];
    float4 o4;
    o4.x = dx * rstd * gg.x + bb.x;
    o4.y = dy * rstd * gg.y + bb.y;
    o4.z = dz * rstd * gg.z + bb.z;
    o4.w = dw * rstd * gg.w + bb.w;
    ((float4*)(hn + (size_t)r * D))[lane] = o4;
}

/* combined[dst, colofs:colofs+128] += hn[src]  (warp per edge)        */
__global__ void scatter_add(const float* __restrict__ hn,
                            const int* __restrict__ src, const int* __restrict__ dst,
                            float* __restrict__ comb, int colofs) {
    int e = (blockIdx.x * blockDim.x + threadIdx.x) >> 5;
    int lane = threadIdx.x & 31;
    if (e >= N_TX) return;
    float4 hv = ((const float4*)(hn + (size_t)src[e] * D))[lane];
    float* c = comb + (size_t)dst[e] * CDIM + colofs + (lane << 2);
    atomicAdd(c + 0, hv.x);
    atomicAdd(c + 1, hv.y);
    atomicAdd(c + 2, hv.z);
    atomicAdd(c + 3, hv.w);
}

/* Final logits: out[m] = dot(x2[m,0:64], W3) + b3   (warp per row)    */
__global__ void final_dot(const float* __restrict__ x2, const float* __restrict__ W3,
                          const float* __restrict__ b3, float* __restrict__ out) {
    int r = (blockIdx.x * blockDim.x + threadIdx.x) >> 5;
    int lane = threadIdx.x & 31;
    if (r >= N_TX) return;
    float2 xv = ((const float2*)(x2 + (size_t)r * 64))[lane];
    float2 wv = ((const float2*)W3)[lane];
    float s = xv.x * wv.x + xv.y * wv.y;
#pragma unroll
    for (int o = 16; o; o >>= 1) s += __shfl_xor_sync(0xFFFFFFFFu, s, o);
    if (lane == 0) out[r] = s + b3[0];
}

/* ------------------------------------------------------------------ */
extern "C" void kernel_launch(void* const* d_in, const int* in_sizes, int n_in,
                              void* d_out, int out_size) {
    const float* tx_x  = (const float*)d_in[0];
    const int*   ent_x = (const int*)d_in[1];
    const int*   e_src = (const int*)d_in[2];
    const int*   e_dst = (const int*)d_in[3];
    const float* emb   = (const float*)d_in[4];
    const float* ln_g  = (const float*)d_in[5];
    const float* ln_b  = (const float*)d_in[6];
    const float* Wq = (const float*)d_in[7];  const float* bq = (const float*)d_in[8];
    const float* Wk = (const float*)d_in[9];  const float* bk = (const float*)d_in[10];
    const float* Wv = (const float*)d_in[11]; const float* bv = (const float*)d_in[12];
    const float* Ws = (const float*)d_in[13]; const float* bs = (const float*)d_in[14];
    const float* W1 = (const float*)d_in[15]; const float* b1 = (const float*)d_in[16];
    const float* W2 = (const float*)d_in[17]; const float* b2 = (const float*)d_in[18];
    const float* W3 = (const float*)d_in[19]; const float* b3 = (const float*)d_in[20];
    float* out = (float*)d_out;

    float *qkvs, *hn, *scores, *ex, *denom, *comb, *x1, *x2, *Bcat, *bcat;
    unsigned* mEnc;
    cudaGetSymbolAddress((void**)&qkvs,   g_qkvs);
    cudaGetSymbolAddress((void**)&hn,     g_hn);
    cudaGetSymbolAddress((void**)&scores, g_scores);
    cudaGetSymbolAddress((void**)&ex,     g_ex);
    cudaGetSymbolAddress((void**)&denom,  g_denom);
    cudaGetSymbolAddress((void**)&mEnc,   g_m);
    cudaGetSymbolAddress((void**)&comb,   g_comb);
    cudaGetSymbolAddress((void**)&x1,     g_x1);
    cudaGetSymbolAddress((void**)&x2,     g_x2);
    cudaGetSymbolAddress((void**)&Bcat,   g_Bcat);
    cudaGetSymbolAddress((void**)&bcat,   g_bcat);

    pack_w<<<(D * QLD + 255) / 256, 256>>>(Wq, Wk, Wv, Ws, bq, bk, bv, bs, Bcat, bcat);
    comb_init<<<(N_TX * (CDIM / 4) + 255) / 256, 256>>>(tx_x, comb);

    for (int t = 0; t < T; t++) {
        const int* idx = ent_x + (size_t)t * N_ENT;
        const int* src = e_src + (size_t)t * N_TX;
        const int* dst = e_dst + (size_t)t * N_TX;
        const float* embt = emb + (size_t)t * N_ENT * D;

        init_md<<<(N_ENT + 255) / 256, 256>>>(mEnc, denom);
        /* q|k|v|skip for all 50000 entities in one gather-GEMM (N=512) */
        sgemm64<<<dim3(QLD / 64, (N_ENT + 63) / 64), 256>>>(
            embt, idx, Bcat, bcat, qkvs, N_ENT, QLD, D, 0);
        edge_scores<<<(N_TX * 32 + 255) / 256, 256>>>(qkvs, src, dst, scores, mEnc);
        edge_exp<<<(N_TX + 255) / 256, 256>>>(scores, dst, mEnc, ex, denom);
        edge_agg<<<(N_TX * 32 + 255) / 256, 256>>>(ex, denom, src, dst, qkvs);
        layernorm<<<(N_ENT * 32 + 255) / 256, 256>>>(qkvs, ln_g + t * D, ln_b + t * D, hn);
        scatter_add<<<(N_TX * 32 + 255) / 256, 256>>>(hn, src, dst, comb, F + t * D);
    }

    /* classifier */
    sgemm64<<<dim3(D / 64, (N_TX + 63) / 64), 256>>>(comb, NULL, W1, b1, x1, N_TX, D, CDIM, 1);
    sgemm64<<<dim3(1, (N_TX + 63) / 64), 256>>>(x1, NULL, W2, b2, x2, N_TX, 64, D, 1);
    final_dot<<<(N_TX * 32 + 255) / 256, 256>>>(x2, W3, b3, out);
}

// round 3
// speedup vs baseline: 1.5463x; 1.5463x over previous
#include <cuda_runtime.h>
#include <cuda_bf16.h>
#include <math.h>
#include <stdint.h>
#include <stddef.h>

#define N_ENT 50000
#define N_TX  40000
#define D     128
#define F     432
#define T     11
#define CDIM  (F + T * D)      /* 1840 */
#define K1PAD 1856             /* 1840 padded to mult of 32 */
#define QLD   512              /* q|k|v|out packed per entity row */
#define EPS   1e-5f
#define SCALE 0.08838834764831845f  /* 1/sqrt(128) */

/* ------------------------------------------------------------------ */
/* Scratch (allocation-free: __device__ globals)                       */
/* ------------------------------------------------------------------ */
__device__ float    g_qkvs[(size_t)N_ENT * QLD];    /* q|k|v|attn-out */
__device__ float    g_hn[(size_t)N_ENT * D];
__device__ float    g_scores[N_TX];
__device__ float    g_ex[N_TX];
__device__ float    g_denom[N_ENT];
__device__ unsigned g_m[N_ENT];
__device__ float    g_comb[(size_t)N_TX * CDIM];
__device__ float    g_x1[(size_t)N_TX * D];
__device__ float    g_x2[(size_t)N_TX * 64];
__device__ float    g_Bcat[D * QLD];
__device__ float    g_bcat[QLD];
/* bf16 hi/lo split weights */
__device__ __nv_bfloat16 g_Bh[D * QLD],    g_Bl[D * QLD];
__device__ __nv_bfloat16 g_W1h[K1PAD * D], g_W1l[K1PAD * D];
__device__ __nv_bfloat16 g_W2h[D * 64],    g_W2l[D * 64];

/* ------------------------------------------------------------------ */
__device__ __forceinline__ unsigned f2o(float f) {
    unsigned u = __float_as_uint(f);
    return (u & 0x80000000u) ? ~u : (u | 0x80000000u);
}
__device__ __forceinline__ float o2f(unsigned u) {
    return (u & 0x80000000u) ? __uint_as_float(u & 0x7FFFFFFFu)
                             : __uint_as_float(~u);
}

/* ------------------------------------------------------------------ */
__global__ void pack_w(const float* __restrict__ Wq, const float* __restrict__ Wk,
                       const float* __restrict__ Wv, const float* __restrict__ Ws,
                       const float* __restrict__ bq, const float* __restrict__ bk,
                       const float* __restrict__ bv, const float* __restrict__ bs,
                       float* __restrict__ Bcat, float* __restrict__ bcat) {
    int i = blockIdx.x * blockDim.x + threadIdx.x;
    if (i >= D * QLD) return;
    int n = i & (QLD - 1);
    int k = i >> 9;
    const float* W = (n < 128) ? Wq : (n < 256) ? Wk : (n < 384) ? Wv : Ws;
    int nn = n & 127;
    Bcat[k * QLD + n] = W[k * 128 + nn];
    if (k == 0) {
        const float* bb = (n < 128) ? bq : (n < 256) ? bk : (n < 384) ? bv : bs;
        bcat[n] = bb[nn];
    }
}

/* split fp32 [Kreal x N] -> bf16 hi/lo [Kpad x N] (zero-padded rows)  */
__global__ void split_w(const float* __restrict__ src,
                        __nv_bfloat16* __restrict__ dh, __nv_bfloat16* __restrict__ dl,
                        int Kreal, int Kpad, int Ncols) {
    int i = blockIdx.x * blockDim.x + threadIdx.x;
    if (i >= Kpad * Ncols) return;
    int k = i / Ncols;
    float v = (k < Kreal) ? src[i] : 0.f;
    __nv_bfloat16 h = __float2bfloat16_rn(v);
    __nv_bfloat16 l = __float2bfloat16_rn(v - __bfloat162float(h));
    dh[i] = h;
    dl[i] = l;
}

/* ------------------------------------------------------------------ */
__global__ void comb_init(const float* __restrict__ tx, float* __restrict__ comb) {
    int i = blockIdx.x * blockDim.x + threadIdx.x;
    const int TOT = N_TX * (CDIM / 4);
    if (i >= TOT) return;
    int row = i / (CDIM / 4);
    int c4  = i - row * (CDIM / 4);
    float4 v = make_float4(0.f, 0.f, 0.f, 0.f);
    if (c4 < F / 4) v = ((const float4*)(tx + (size_t)row * F))[c4];
    ((float4*)(comb + (size_t)row * CDIM))[c4] = v;
}

__global__ void init_md(unsigned* __restrict__ m, float* __restrict__ denom) {
    int i = blockIdx.x * blockDim.x + threadIdx.x;
    if (i < N_ENT) { m[i] = 0u; denom[i] = 0.f; }
}

/* ------------------------------------------------------------------ */
/* Tensor-core GEMM with bf16 hi/lo split (3-product fp32 emulation).  */
/* C[M,N] = gather(A)[M,Kreal] @ Bsplit[Kpad,N] + bias, opt relu.      */
/* BM=128 BN=64 BK=32, 256 thr, 8 warps 4x2, warp tile 32x32.          */
/* Requires: Kreal%16==0, Kpad%32==0, N%64==0 (grid exact), A 16B al.  */
/* ------------------------------------------------------------------ */
#define BM 128
#define BN 64
#define BK 32
#define ASTR 40   /* SMEM row stride (bf16 elems) for A tiles */
#define BSTR 72   /* SMEM row stride for B tiles */

__device__ __forceinline__ void ldsm4(uint32_t* r, const void* p) {
    uint32_t a = (uint32_t)__cvta_generic_to_shared(p);
    asm volatile("ldmatrix.sync.aligned.m8n8.x4.shared.b16 {%0,%1,%2,%3}, [%4];"
                 : "=r"(r[0]), "=r"(r[1]), "=r"(r[2]), "=r"(r[3]) : "r"(a));
}
__device__ __forceinline__ void ldsm4t(uint32_t* r, const void* p) {
    uint32_t a = (uint32_t)__cvta_generic_to_shared(p);
    asm volatile("ldmatrix.sync.aligned.m8n8.x4.trans.shared.b16 {%0,%1,%2,%3}, [%4];"
                 : "=r"(r[0]), "=r"(r[1]), "=r"(r[2]), "=r"(r[3]) : "r"(a));
}
__device__ __forceinline__ void mma16816(float* c, const uint32_t* a, const uint32_t* b) {
    asm volatile(
        "mma.sync.aligned.m16n8k16.row.col.f32.bf16.bf16.f32 "
        "{%0,%1,%2,%3}, {%4,%5,%6,%7}, {%8,%9}, {%0,%1,%2,%3};\n"
        : "+f"(c[0]), "+f"(c[1]), "+f"(c[2]), "+f"(c[3])
        : "r"(a[0]), "r"(a[1]), "r"(a[2]), "r"(a[3]), "r"(b[0]), "r"(b[1]));
}

__global__ void __launch_bounds__(256) gemm_bf16x2(
    const float* __restrict__ A, const int* __restrict__ rowidx,
    const __nv_bfloat16* __restrict__ Bhg, const __nv_bfloat16* __restrict__ Blg,
    const float* __restrict__ bias, float* __restrict__ C,
    int M, int N, int Kreal, int Kpad, int relu)
{
    __shared__ __nv_bfloat16 Ah[BM][ASTR];
    __shared__ __nv_bfloat16 Al[BM][ASTR];
    __shared__ __nv_bfloat16 Bhs[BK][BSTR];
    __shared__ __nv_bfloat16 Bls[BK][BSTR];

    const int tid  = threadIdx.x;
    const int lane = tid & 31;
    const int warp = tid >> 5;
    const int wm   = warp >> 1;          /* 0..3 */
    const int wn   = warp & 1;           /* 0..1 */
    const int m0   = blockIdx.y * BM;
    const int n0   = blockIdx.x * BN;

    /* A loader: thread -> (row, 16-col half) */
    const int arow  = tid >> 1;          /* 0..127 */
    const int acolg = (tid & 1) << 4;    /* 0 or 16 */
    const float* aptr = NULL;
    {
        int gm = m0 + arow;
        if (gm < M) {
            int r = rowidx ? rowidx[gm] : gm;
            aptr = A + (size_t)r * Kreal;
        }
    }
    /* B loader: thread -> (row 0..31, 8-col group) */
    const int brow  = tid >> 3;
    const int bcolg = (tid & 7) << 3;

    float acc[2][4][4];
#pragma unroll
    for (int i = 0; i < 2; i++)
#pragma unroll
        for (int j = 0; j < 4; j++)
#pragma unroll
            for (int l = 0; l < 4; l++) acc[i][j][l] = 0.f;

    for (int k0 = 0; k0 < Kpad; k0 += BK) {
        /* ---- load + split A chunk ---- */
        float4 f[4];
        if (aptr && (k0 + acolg) < Kreal) {
            const float4* p = (const float4*)(aptr + k0 + acolg);
            f[0] = p[0]; f[1] = p[1]; f[2] = p[2]; f[3] = p[3];
        } else {
            f[0] = f[1] = f[2] = f[3] = make_float4(0.f, 0.f, 0.f, 0.f);
        }
        const float* fv = (const float*)f;
#pragma unroll
        for (int j = 0; j < 8; j++) {
            float x0 = fv[2 * j], x1 = fv[2 * j + 1];
            __nv_bfloat16 h0 = __float2bfloat16_rn(x0);
            __nv_bfloat16 l0 = __float2bfloat16_rn(x0 - __bfloat162float(h0));
            __nv_bfloat16 h1 = __float2bfloat16_rn(x1);
            __nv_bfloat16 l1 = __float2bfloat16_rn(x1 - __bfloat162float(h1));
            __nv_bfloat162 hp; hp.x = h0; hp.y = h1;
            __nv_bfloat162 lp; lp.x = l0; lp.y = l1;
            *(__nv_bfloat162*)&Ah[arow][acolg + 2 * j] = hp;
            *(__nv_bfloat162*)&Al[arow][acolg + 2 * j] = lp;
        }
        /* ---- load B chunk (prepacked bf16) ---- */
        {
            size_t off = (size_t)(k0 + brow) * N + n0 + bcolg;
            uint4 vh = *(const uint4*)(Bhg + off);
            uint4 vl = *(const uint4*)(Blg + off);
            *(uint4*)&Bhs[brow][bcolg] = vh;
            *(uint4*)&Bls[brow][bcolg] = vl;
        }
        __syncthreads();

#pragma unroll
        for (int ks = 0; ks < 2; ks++) {
            const int kk = ks << 4;
            uint32_t afh[2][4], afl[2][4];
#pragma unroll
            for (int mt = 0; mt < 2; mt++) {
                const int r = wm * 32 + mt * 16 + (lane & 15);
                const int c = kk + ((lane >> 4) << 3);
                ldsm4(afh[mt], &Ah[r][c]);
                ldsm4(afl[mt], &Al[r][c]);
            }
            uint32_t bfh[2][4], bfl[2][4];
#pragma unroll
            for (int nc = 0; nc < 2; nc++) {
                const int r = kk + (lane & 15);
                const int c = wn * 32 + nc * 16 + ((lane >> 4) << 3);
                ldsm4t(bfh[nc], &Bhs[r][c]);
                ldsm4t(bfl[nc], &Bls[r][c]);
            }
#pragma unroll
            for (int mt = 0; mt < 2; mt++)
#pragma unroll
                for (int nt = 0; nt < 4; nt++) {
                    const int nc = nt >> 1, p = (nt & 1) << 1;
                    uint32_t bh2[2] = { bfh[nc][p], bfh[nc][p + 1] };
                    uint32_t bl2[2] = { bfl[nc][p], bfl[nc][p + 1] };
                    mma16816(acc[mt][nt], afh[mt], bh2);
                    mma16816(acc[mt][nt], afl[mt], bh2);
                    mma16816(acc[mt][nt], afh[mt], bl2);
                }
        }
        __syncthreads();
    }

    /* ---- epilogue ---- */
#pragma unroll
    for (int mt = 0; mt < 2; mt++)
#pragma unroll
        for (int nt = 0; nt < 4; nt++) {
            const int col = n0 + wn * 32 + nt * 8 + ((lane & 3) << 1);
            const float bx = bias[col], by = bias[col + 1];
            const int r0 = m0 + wm * 32 + mt * 16 + (lane >> 2);
            float o0 = acc[mt][nt][0] + bx, o1 = acc[mt][nt][1] + by;
            float o2 = acc[mt][nt][2] + bx, o3 = acc[mt][nt][3] + by;
            if (relu) {
                o0 = fmaxf(o0, 0.f); o1 = fmaxf(o1, 0.f);
                o2 = fmaxf(o2, 0.f); o3 = fmaxf(o3, 0.f);
            }
            if (r0 < M) { float2 v = make_float2(o0, o1); *(float2*)(C + (size_t)r0 * N + col) = v; }
            if (r0 + 8 < M) { float2 v = make_float2(o2, o3); *(float2*)(C + (size_t)(r0 + 8) * N + col) = v; }
        }
}

/* ------------------------------------------------------------------ */
/* Edge / softmax / LN / scatter kernels (unchanged, fp32)             */
/* ------------------------------------------------------------------ */
__global__ void edge_scores(const float* __restrict__ qkvs,
                            const int* __restrict__ src, const int* __restrict__ dst,
                            float* __restrict__ scores, unsigned* __restrict__ mEnc) {
    int e = (blockIdx.x * blockDim.x + threadIdx.x) >> 5;
    int lane = threadIdx.x & 31;
    if (e >= N_TX) return;
    int dd = dst[e], ss = src[e];
    float4 qv = ((const float4*)(qkvs + (size_t)dd * QLD))[lane];
    float4 kv = ((const float4*)(qkvs + (size_t)ss * QLD + 128))[lane];
    float acc = qv.x * kv.x + qv.y * kv.y + qv.z * kv.z + qv.w * kv.w;
#pragma unroll
    for (int o = 16; o; o >>= 1) acc += __shfl_xor_sync(0xFFFFFFFFu, acc, o);
    acc *= SCALE;
    if (lane == 0) {
        scores[e] = acc;
        atomicMax(&mEnc[dd], f2o(acc));
    }
}

__global__ void edge_exp(const float* __restrict__ scores, const int* __restrict__ dst,
                         const unsigned* __restrict__ mEnc,
                         float* __restrict__ ex, float* __restrict__ denom) {
    int e = blockIdx.x * blockDim.x + threadIdx.x;
    if (e >= N_TX) return;
    int dd = dst[e];
    float v = expf(scores[e] - o2f(mEnc[dd]));
    ex[e] = v;
    atomicAdd(&denom[dd], v);
}

__global__ void edge_agg(const float* __restrict__ ex, const float* __restrict__ denom,
                         const int* __restrict__ src, const int* __restrict__ dst,
                         float* __restrict__ qkvs) {
    int e = (blockIdx.x * blockDim.x + threadIdx.x) >> 5;
    int lane = threadIdx.x & 31;
    if (e >= N_TX) return;
    int dd = dst[e], ss = src[e];
    float alpha = ex[e] / denom[dd];
    float4 vv = ((const float4*)(qkvs + (size_t)ss * QLD + 256))[lane];
    float* o = qkvs + (size_t)dd * QLD + 384 + (lane << 2);
    atomicAdd(o + 0, alpha * vv.x);
    atomicAdd(o + 1, alpha * vv.y);
    atomicAdd(o + 2, alpha * vv.z);
    atomicAdd(o + 3, alpha * vv.w);
}

__global__ void layernorm(const float* __restrict__ qkvs,
                          const float* __restrict__ g, const float* __restrict__ b,
                          float* __restrict__ hn) {
    int r = (blockIdx.x * blockDim.x + threadIdx.x) >> 5;
    int lane = threadIdx.x & 31;
    if (r >= N_ENT) return;
    float4 x = ((const float4*)(qkvs + (size_t)r * QLD + 384))[lane];
    float s = x.x + x.y + x.z + x.w;
#pragma unroll
    for (int o = 16; o; o >>= 1) s += __shfl_xor_sync(0xFFFFFFFFu, s, o);
    float mu = s * (1.f / 128.f);
    float dx = x.x - mu, dy = x.y - mu, dz = x.z - mu, dw = x.w - mu;
    float v = dx * dx + dy * dy + dz * dz + dw * dw;
#pragma unroll
    for (int o = 16; o; o >>= 1) v += __shfl_xor_sync(0xFFFFFFFFu, v, o);
    float rstd = rsqrtf(v * (1.f / 128.f) + EPS);
    float4 gg = ((const float4*)g)[lane];
    float4 bb = ((const float4*)b)[lane];
    float4 o4;
    o4.x = dx * rstd * gg.x + bb.x;
    o4.y = dy * rstd * gg.y + bb.y;
    o4.z = dz * rstd * gg.z + bb.z;
    o4.w = dw * rstd * gg.w + bb.w;
    ((float4*)(hn + (size_t)r * D))[lane] = o4;
}

__global__ void scatter_add(const float* __restrict__ hn,
                            const int* __restrict__ src, const int* __restrict__ dst,
                            float* __restrict__ comb, int colofs) {
    int e = (blockIdx.x * blockDim.x + threadIdx.x) >> 5;
    int lane = threadIdx.x & 31;
    if (e >= N_TX) return;
    float4 hv = ((const float4*)(hn + (size_t)src[e] * D))[lane];
    float* c = comb + (size_t)dst[e] * CDIM + colofs + (lane << 2);
    atomicAdd(c + 0, hv.x);
    atomicAdd(c + 1, hv.y);
    atomicAdd(c + 2, hv.z);
    atomicAdd(c + 3, hv.w);
}

__global__ void final_dot(const float* __restrict__ x2, const float* __restrict__ W3,
                          const float* __restrict__ b3, float* __restrict__ out) {
    int r = (blockIdx.x * blockDim.x + threadIdx.x) >> 5;
    int lane = threadIdx.x & 31;
    if (r >= N_TX) return;
    float2 xv = ((const float2*)(x2 + (size_t)r * 64))[lane];
    float2 wv = ((const float2*)W3)[lane];
    float s = xv.x * wv.x + xv.y * wv.y;
#pragma unroll
    for (int o = 16; o; o >>= 1) s += __shfl_xor_sync(0xFFFFFFFFu, s, o);
    if (lane == 0) out[r] = s + b3[0];
}

/* ------------------------------------------------------------------ */
extern "C" void kernel_launch(void* const* d_in, const int* in_sizes, int n_in,
                              void* d_out, int out_size) {
    const float* tx_x  = (const float*)d_in[0];
    const int*   ent_x = (const int*)d_in[1];
    const int*   e_src = (const int*)d_in[2];
    const int*   e_dst = (const int*)d_in[3];
    const float* emb   = (const float*)d_in[4];
    const float* ln_g  = (const float*)d_in[5];
    const float* ln_b  = (const float*)d_in[6];
    const float* Wq = (const float*)d_in[7];  const float* bq = (const float*)d_in[8];
    const float* Wk = (const float*)d_in[9];  const float* bk = (const float*)d_in[10];
    const float* Wv = (const float*)d_in[11]; const float* bv = (const float*)d_in[12];
    const float* Ws = (const float*)d_in[13]; const float* bs = (const float*)d_in[14];
    const float* W1 = (const float*)d_in[15]; const float* b1 = (const float*)d_in[16];
    const float* W2 = (const float*)d_in[17]; const float* b2 = (const float*)d_in[18];
    const float* W3 = (const float*)d_in[19]; const float* b3 = (const float*)d_in[20];
    float* out = (float*)d_out;

    float *qkvs, *hn, *scores, *ex, *denom, *comb, *x1, *x2, *Bcat, *bcat;
    unsigned* mEnc;
    __nv_bfloat16 *Bh, *Bl, *W1h, *W1l, *W2h, *W2l;
    cudaGetSymbolAddress((void**)&qkvs,   g_qkvs);
    cudaGetSymbolAddress((void**)&hn,     g_hn);
    cudaGetSymbolAddress((void**)&scores, g_scores);
    cudaGetSymbolAddress((void**)&ex,     g_ex);
    cudaGetSymbolAddress((void**)&denom,  g_denom);
    cudaGetSymbolAddress((void**)&mEnc,   g_m);
    cudaGetSymbolAddress((void**)&comb,   g_comb);
    cudaGetSymbolAddress((void**)&x1,     g_x1);
    cudaGetSymbolAddress((void**)&x2,     g_x2);
    cudaGetSymbolAddress((void**)&Bcat,   g_Bcat);
    cudaGetSymbolAddress((void**)&bcat,   g_bcat);
    cudaGetSymbolAddress((void**)&Bh,     g_Bh);
    cudaGetSymbolAddress((void**)&Bl,     g_Bl);
    cudaGetSymbolAddress((void**)&W1h,    g_W1h);
    cudaGetSymbolAddress((void**)&W1l,    g_W1l);
    cudaGetSymbolAddress((void**)&W2h,    g_W2h);
    cudaGetSymbolAddress((void**)&W2l,    g_W2l);

    pack_w<<<(D * QLD + 255) / 256, 256>>>(Wq, Wk, Wv, Ws, bq, bk, bv, bs, Bcat, bcat);
    split_w<<<(D * QLD + 255) / 256, 256>>>(Bcat, Bh, Bl, D, D, QLD);
    split_w<<<(K1PAD * D + 255) / 256, 256>>>(W1, W1h, W1l, CDIM, K1PAD, D);
    split_w<<<(D * 64 + 255) / 256, 256>>>(W2, W2h, W2l, D, D, 64);
    comb_init<<<(N_TX * (CDIM / 4) + 255) / 256, 256>>>(tx_x, comb);

    for (int t = 0; t < T; t++) {
        const int* idx = ent_x + (size_t)t * N_ENT;
        const int* src = e_src + (size_t)t * N_TX;
        const int* dst = e_dst + (size_t)t * N_TX;
        const float* embt = emb + (size_t)t * N_ENT * D;

        init_md<<<(N_ENT + 255) / 256, 256>>>(mEnc, denom);
        gemm_bf16x2<<<dim3(QLD / BN, (N_ENT + BM - 1) / BM), 256>>>(
            embt, idx, Bh, Bl, bcat, qkvs, N_ENT, QLD, D, D, 0);
        edge_scores<<<(N_TX * 32 + 255) / 256, 256>>>(qkvs, src, dst, scores, mEnc);
        edge_exp<<<(N_TX + 255) / 256, 256>>>(scores, dst, mEnc, ex, denom);
        edge_agg<<<(N_TX * 32 + 255) / 256, 256>>>(ex, denom, src, dst, qkvs);
        layernorm<<<(N_ENT * 32 + 255) / 256, 256>>>(qkvs, ln_g + t * D, ln_b + t * D, hn);
        scatter_add<<<(N_TX * 32 + 255) / 256, 256>>>(hn, src, dst, comb, F + t * D);
    }

    /* classifier */
    gemm_bf16x2<<<dim3(D / BN, (N_TX + BM - 1) / BM), 256>>>(
        comb, NULL, W1h, W1l, b1, x1, N_TX, D, CDIM, K1PAD, 1);
    gemm_bf16x2<<<dim3(1, (N_TX + BM - 1) / BM), 256>>>(
        x1, NULL, W2h, W2l, b2, x2, N_TX, 64, D, D, 1);
    final_dot<<<(N_TX * 32 + 255) / 256, 256>>>(x2, W3, b3, out);
}

// round 4
// speedup vs baseline: 1.5664x; 1.0130x over previous
#include <cuda_runtime.h>
#include <cuda_bf16.h>
#include <math.h>
#include <stdint.h>
#include <stddef.h>

#define N_ENT 50000
#define N_TX  40000
#define D     128
#define F     432
#define T     11
#define CDIM  (F + T * D)      /* 1840 */
#define K1PAD 1856             /* 1840 padded to mult of 32 */
#define QLD   512
#define EPS   1e-5f
#define SCALE 0.08838834764831845f

#define MPAD_E 50048           /* 391*128 */
#define MPAD_T 40064           /* 313*128 */

/* ------------------------------------------------------------------ */
__device__ float    g_qkvs[(size_t)N_ENT * QLD];
__device__ float    g_hn[(size_t)N_ENT * D];
__device__ float    g_ex[N_TX];
__device__ float    g_denom[N_ENT];
__device__ float    g_comb[(size_t)MPAD_T * CDIM];  /* rows >=40000 stay 0 */
__device__ float    g_x1[(size_t)N_TX * D];
__device__ float    g_x2[(size_t)N_TX * 64];
__device__ float    g_Bcat[D * QLD];
__device__ float    g_bcat[QLD];
__device__ __nv_bfloat16 g_Ah[(size_t)MPAD_E * D], g_Al[(size_t)MPAD_E * D];
__device__ __nv_bfloat16 g_Bh[D * QLD],    g_Bl[D * QLD];
__device__ __nv_bfloat16 g_W1h[K1PAD * D], g_W1l[K1PAD * D];
__device__ __nv_bfloat16 g_W2h[D * 64],    g_W2l[D * 64];

/* ------------------------------------------------------------------ */
__global__ void pack_w(const float* __restrict__ Wq, const float* __restrict__ Wk,
                       const float* __restrict__ Wv, const float* __restrict__ Ws,
                       const float* __restrict__ bq, const float* __restrict__ bk,
                       const float* __restrict__ bv, const float* __restrict__ bs,
                       float* __restrict__ Bcat, float* __restrict__ bcat) {
    int i = blockIdx.x * blockDim.x + threadIdx.x;
    if (i >= D * QLD) return;
    int n = i & (QLD - 1);
    int k = i >> 9;
    const float* W = (n < 128) ? Wq : (n < 256) ? Wk : (n < 384) ? Wv : Ws;
    int nn = n & 127;
    Bcat[k * QLD + n] = W[k * 128 + nn];
    if (k == 0) {
        const float* bb = (n < 128) ? bq : (n < 256) ? bk : (n < 384) ? bv : bs;
        bcat[n] = bb[nn];
    }
}

__global__ void split_w(const float* __restrict__ src,
                        __nv_bfloat16* __restrict__ dh, __nv_bfloat16* __restrict__ dl,
                        int Kreal, int Kpad, int Ncols) {
    int i = blockIdx.x * blockDim.x + threadIdx.x;
    if (i >= Kpad * Ncols) return;
    int k = i / Ncols;
    float v = (k < Kreal) ? src[i] : 0.f;
    __nv_bfloat16 h = __float2bfloat16_rn(v);
    __nv_bfloat16 l = __float2bfloat16_rn(v - __bfloat162float(h));
    dh[i] = h;
    dl[i] = l;
}

/* gather emb rows by idx and split to bf16 hi/lo, one float4 per thr  */
__global__ void gather_split(const float* __restrict__ embt, const int* __restrict__ idx,
                             __nv_bfloat16* __restrict__ Ah, __nv_bfloat16* __restrict__ Al) {
    int i = blockIdx.x * blockDim.x + threadIdx.x;
    if (i >= N_ENT * (D / 4)) return;
    int row = i >> 5;
    int c4  = i & 31;
    int r = idx[row];
    float4 v = ((const float4*)(embt + (size_t)r * D))[c4];
    float vv[4] = { v.x, v.y, v.z, v.w };
    __nv_bfloat16 h[4], l[4];
#pragma unroll
    for (int j = 0; j < 4; j++) {
        h[j] = __float2bfloat16_rn(vv[j]);
        l[j] = __float2bfloat16_rn(vv[j] - __bfloat162float(h[j]));
    }
    size_t o = (size_t)row * D + (c4 << 2);
    *(uint2*)(Ah + o) = *(uint2*)h;
    *(uint2*)(Al + o) = *(uint2*)l;
}

__global__ void comb_init(const float* __restrict__ tx, float* __restrict__ comb) {
    int i = blockIdx.x * blockDim.x + threadIdx.x;
    const int TOT = N_TX * (CDIM / 4);
    if (i >= TOT) return;
    int row = i / (CDIM / 4);
    int c4  = i - row * (CDIM / 4);
    float4 v = make_float4(0.f, 0.f, 0.f, 0.f);
    if (c4 < F / 4) v = ((const float4*)(tx + (size_t)row * F))[c4];
    ((float4*)(comb + (size_t)row * CDIM))[c4] = v;
}

__global__ void init_d(float* __restrict__ denom) {
    int i = blockIdx.x * blockDim.x + threadIdx.x;
    if (i < N_ENT) denom[i] = 0.f;
}

/* ------------------------------------------------------------------ */
__device__ __forceinline__ void ldsm4(uint32_t* r, const void* p) {
    uint32_t a = (uint32_t)__cvta_generic_to_shared(p);
    asm volatile("ldmatrix.sync.aligned.m8n8.x4.shared.b16 {%0,%1,%2,%3}, [%4];"
                 : "=r"(r[0]), "=r"(r[1]), "=r"(r[2]), "=r"(r[3]) : "r"(a));
}
__device__ __forceinline__ void ldsm4t(uint32_t* r, const void* p) {
    uint32_t a = (uint32_t)__cvta_generic_to_shared(p);
    asm volatile("ldmatrix.sync.aligned.m8n8.x4.trans.shared.b16 {%0,%1,%2,%3}, [%4];"
                 : "=r"(r[0]), "=r"(r[1]), "=r"(r[2]), "=r"(r[3]) : "r"(a));
}
__device__ __forceinline__ void mma16816(float* c, const uint32_t* a, const uint32_t* b) {
    asm volatile(
        "mma.sync.aligned.m16n8k16.row.col.f32.bf16.bf16.f32 "
        "{%0,%1,%2,%3}, {%4,%5,%6,%7}, {%8,%9}, {%0,%1,%2,%3};\n"
        : "+f"(c[0]), "+f"(c[1]), "+f"(c[2]), "+f"(c[3])
        : "r"(a[0]), "r"(a[1]), "r"(a[2]), "r"(a[3]), "r"(b[0]), "r"(b[1]));
}

/* ------------------------------------------------------------------ */
/* gemm128: C[M,N] = A[M,K] @ B[K,N] + bias, BM=BN=128, BK=32.         */
/* SPLITA=1: A pre-split bf16 (rows padded -> no load guards).         */
/* SPLITA=0: A fp32 (rows padded), split on the fly.                   */
/* Requires grid exact in N, rows padded to BM multiple.               */
/* ------------------------------------------------------------------ */
#define ASTR  40
#define BSTR2 144

template<int SPLITA>
__global__ void __launch_bounds__(256) gemm128(
    const float* __restrict__ Afp,
    const __nv_bfloat16* __restrict__ Ahg, const __nv_bfloat16* __restrict__ Alg,
    const __nv_bfloat16* __restrict__ Bhg, const __nv_bfloat16* __restrict__ Blg,
    const float* __restrict__ bias, float* __restrict__ C,
    int M, int N, int Kreal, int Kpad, int relu)
{
    __shared__ __nv_bfloat16 Ahs[128][ASTR];
    __shared__ __nv_bfloat16 Als[128][ASTR];
    __shared__ __nv_bfloat16 Bhs[32][BSTR2];
    __shared__ __nv_bfloat16 Bls[32][BSTR2];

    const int tid  = threadIdx.x;
    const int lane = tid & 31;
    const int warp = tid >> 5;
    const int wm   = warp >> 1;
    const int wn   = warp & 1;
    const int m0   = blockIdx.y * 128;
    const int n0   = blockIdx.x * 128;

    const int arow  = tid >> 1;
    const int acolg = (tid & 1) << 4;
    const int brow  = tid >> 3;
    const int bcol  = (tid & 7) << 4;

    float acc[2][8][4];
#pragma unroll
    for (int a = 0; a < 2; a++)
#pragma unroll
        for (int b = 0; b < 8; b++)
#pragma unroll
            for (int c = 0; c < 4; c++) acc[a][b][c] = 0.f;

    uint4  sAh[2], sAl[2];
    float4 sAf[4];
    uint4  sBh[2], sBl[2];

#define LOADT(K0)                                                              \
    do {                                                                       \
        if (SPLITA) {                                                          \
            size_t ao = (size_t)(m0 + arow) * Kreal + (K0) + acolg;            \
            sAh[0] = *(const uint4*)(Ahg + ao);                                \
            sAh[1] = *(const uint4*)(Ahg + ao + 8);                            \
            sAl[0] = *(const uint4*)(Alg + ao);                                \
            sAl[1] = *(const uint4*)(Alg + ao + 8);                            \
        } else {                                                               \
            if ((K0) + acolg < Kreal) {                                        \
                const float4* p = (const float4*)(Afp +                        \
                    (size_t)(m0 + arow) * Kreal + (K0) + acolg);               \
                sAf[0] = p[0]; sAf[1] = p[1]; sAf[2] = p[2]; sAf[3] = p[3];    \
            } else {                                                           \
                sAf[0] = sAf[1] = sAf[2] = sAf[3] =                            \
                    make_float4(0.f, 0.f, 0.f, 0.f);                           \
            }                                                                  \
        }                                                                      \
        size_t bo = (size_t)((K0) + brow) * N + n0 + bcol;                     \
        sBh[0] = *(const uint4*)(Bhg + bo);                                    \
        sBh[1] = *(const uint4*)(Bhg + bo + 8);                                \
        sBl[0] = *(const uint4*)(Blg + bo);                                    \
        sBl[1] = *(const uint4*)(Blg + bo + 8);                                \
    } while (0)

    LOADT(0);

    for (int k0 = 0; k0 < Kpad; k0 += 32) {
        /* commit staged tile to SMEM */
        if (SPLITA) {
            *(uint4*)&Ahs[arow][acolg]     = sAh[0];
            *(uint4*)&Ahs[arow][acolg + 8] = sAh[1];
            *(uint4*)&Als[arow][acolg]     = sAl[0];
            *(uint4*)&Als[arow][acolg + 8] = sAl[1];
        } else {
            const float* fv = (const float*)sAf;
#pragma unroll
            for (int j = 0; j < 8; j++) {
                float x0 = fv[2 * j], x1 = fv[2 * j + 1];
                __nv_bfloat16 h0 = __float2bfloat16_rn(x0);
                __nv_bfloat16 l0 = __float2bfloat16_rn(x0 - __bfloat162float(h0));
                __nv_bfloat16 h1 = __float2bfloat16_rn(x1);
                __nv_bfloat16 l1 = __float2bfloat16_rn(x1 - __bfloat162float(h1));
                __nv_bfloat162 hp; hp.x = h0; hp.y = h1;
                __nv_bfloat162 lp; lp.x = l0; lp.y = l1;
                *(__nv_bfloat162*)&Ahs[arow][acolg + 2 * j] = hp;
                *(__nv_bfloat162*)&Als[arow][acolg + 2 * j] = lp;
            }
        }
        *(uint4*)&Bhs[brow][bcol]     = sBh[0];
        *(uint4*)&Bhs[brow][bcol + 8] = sBh[1];
        *(uint4*)&Bls[brow][bcol]     = sBl[0];
        *(uint4*)&Bls[brow][bcol + 8] = sBl[1];
        __syncthreads();

        /* issue next tile's global loads early */
        int kn = k0 + 32;
        if (kn < Kpad) LOADT(kn);

#pragma unroll
        for (int ks = 0; ks < 2; ks++) {
            const int kk = ks << 4;
            uint32_t afh[2][4], afl[2][4];
#pragma unroll
            for (int mt = 0; mt < 2; mt++) {
                const int r = wm * 32 + mt * 16 + (lane & 15);
                const int c = kk + ((lane >> 4) << 3);
                ldsm4(afh[mt], &Ahs[r][c]);
                ldsm4(afl[mt], &Als[r][c]);
            }
            uint32_t bfh[4][4], bfl[4][4];
#pragma unroll
            for (int nc = 0; nc < 4; nc++) {
                const int r = kk + (lane & 15);
                const int c = wn * 64 + nc * 16 + ((lane >> 4) << 3);
                ldsm4t(bfh[nc], &Bhs[r][c]);
                ldsm4t(bfl[nc], &Bls[r][c]);
            }
#pragma unroll
            for (int mt = 0; mt < 2; mt++)
#pragma unroll
                for (int nt = 0; nt < 8; nt++) {
                    const int nc = nt >> 1, p = (nt & 1) << 1;
                    uint32_t bh2[2] = { bfh[nc][p], bfh[nc][p + 1] };
                    uint32_t bl2[2] = { bfl[nc][p], bfl[nc][p + 1] };
                    mma16816(acc[mt][nt], afh[mt], bh2);
                    mma16816(acc[mt][nt], afl[mt], bh2);
                    mma16816(acc[mt][nt], afh[mt], bl2);
                }
        }
        __syncthreads();
    }
#undef LOADT

#pragma unroll
    for (int mt = 0; mt < 2; mt++)
#pragma unroll
        for (int nt = 0; nt < 8; nt++) {
            const int col = n0 + wn * 64 + nt * 8 + ((lane & 3) << 1);
            const float bx = bias[col], by = bias[col + 1];
            const int r0 = m0 + wm * 32 + mt * 16 + (lane >> 2);
            float o0 = acc[mt][nt][0] + bx, o1 = acc[mt][nt][1] + by;
            float o2 = acc[mt][nt][2] + bx, o3 = acc[mt][nt][3] + by;
            if (relu) {
                o0 = fmaxf(o0, 0.f); o1 = fmaxf(o1, 0.f);
                o2 = fmaxf(o2, 0.f); o3 = fmaxf(o3, 0.f);
            }
            if (r0 < M)     { float2 v = make_float2(o0, o1); *(float2*)(C + (size_t)r0 * N + col) = v; }
            if (r0 + 8 < M) { float2 v = make_float2(o2, o3); *(float2*)(C + (size_t)(r0 + 8) * N + col) = v; }
        }
}

/* ------------------------------------------------------------------ */
/* round-3 BN=64 GEMM kept for the small GEMM2 (N=64)                  */
/* ------------------------------------------------------------------ */
#define BSTR 72
__global__ void __launch_bounds__(256) gemm_bf16x2(
    const float* __restrict__ A,
    const __nv_bfloat16* __restrict__ Bhg, const __nv_bfloat16* __restrict__ Blg,
    const float* __restrict__ bias, float* __restrict__ C,
    int M, int N, int Kreal, int Kpad, int relu)
{
    __shared__ __nv_bfloat16 Ah[128][ASTR];
    __shared__ __nv_bfloat16 Al[128][ASTR];
    __shared__ __nv_bfloat16 Bhs[32][BSTR];
    __shared__ __nv_bfloat16 Bls[32][BSTR];

    const int tid  = threadIdx.x;
    const int lane = tid & 31;
    const int warp = tid >> 5;
    const int wm   = warp >> 1;
    const int wn   = warp & 1;
    const int m0   = blockIdx.y * 128;
    const int n0   = blockIdx.x * 64;

    const int arow  = tid >> 1;
    const int acolg = (tid & 1) << 4;
    const float* aptr = NULL;
    {
        int gm = m0 + arow;
        if (gm < M) aptr = A + (size_t)gm * Kreal;
    }
    const int brow  = tid >> 3;
    const int bcolg = (tid & 7) << 3;

    float acc[2][4][4];
#pragma unroll
    for (int i = 0; i < 2; i++)
#pragma unroll
        for (int j = 0; j < 4; j++)
#pragma unroll
            for (int l = 0; l < 4; l++) acc[i][j][l] = 0.f;

    for (int k0 = 0; k0 < Kpad; k0 += 32) {
        float4 f[4];
        if (aptr && (k0 + acolg) < Kreal) {
            const float4* p = (const float4*)(aptr + k0 + acolg);
            f[0] = p[0]; f[1] = p[1]; f[2] = p[2]; f[3] = p[3];
        } else {
            f[0] = f[1] = f[2] = f[3] = make_float4(0.f, 0.f, 0.f, 0.f);
        }
        const float* fv = (const float*)f;
#pragma unroll
        for (int j = 0; j < 8; j++) {
            float x0 = fv[2 * j], x1 = fv[2 * j + 1];
            __nv_bfloat16 h0 = __float2bfloat16_rn(x0);
            __nv_bfloat16 l0 = __float2bfloat16_rn(x0 - __bfloat162float(h0));
            __nv_bfloat16 h1 = __float2bfloat16_rn(x1);
            __nv_bfloat16 l1 = __float2bfloat16_rn(x1 - __bfloat162float(h1));
            __nv_bfloat162 hp; hp.x = h0; hp.y = h1;
            __nv_bfloat162 lp; lp.x = l0; lp.y = l1;
            *(__nv_bfloat162*)&Ah[arow][acolg + 2 * j] = hp;
            *(__nv_bfloat162*)&Al[arow][acolg + 2 * j] = lp;
        }
        {
            size_t off = (size_t)(k0 + brow) * N + n0 + bcolg;
            uint4 vh = *(const uint4*)(Bhg + off);
            uint4 vl = *(const uint4*)(Blg + off);
            *(uint4*)&Bhs[brow][bcolg] = vh;
            *(uint4*)&Bls[brow][bcolg] = vl;
        }
        __syncthreads();

#pragma unroll
        for (int ks = 0; ks < 2; ks++) {
            const int kk = ks << 4;
            uint32_t afh[2][4], afl[2][4];
#pragma unroll
            for (int mt = 0; mt < 2; mt++) {
                const int r = wm * 32 + mt * 16 + (lane & 15);
                const int c = kk + ((lane >> 4) << 3);
                ldsm4(afh[mt], &Ah[r][c]);
                ldsm4(afl[mt], &Al[r][c]);
            }
            uint32_t bfh[2][4], bfl[2][4];
#pragma unroll
            for (int nc = 0; nc < 2; nc++) {
                const int r = kk + (lane & 15);
                const int c = wn * 32 + nc * 16 + ((lane >> 4) << 3);
                ldsm4t(bfh[nc], &Bhs[r][c]);
                ldsm4t(bfl[nc], &Bls[r][c]);
            }
#pragma unroll
            for (int mt = 0; mt < 2; mt++)
#pragma unroll
                for (int nt = 0; nt < 4; nt++) {
                    const int nc = nt >> 1, p = (nt & 1) << 1;
                    uint32_t bh2[2] = { bfh[nc][p], bfh[nc][p + 1] };
                    uint32_t bl2[2] = { bfl[nc][p], bfl[nc][p + 1] };
                    mma16816(acc[mt][nt], afh[mt], bh2);
                    mma16816(acc[mt][nt], afl[mt], bh2);
                    mma16816(acc[mt][nt], afh[mt], bl2);
                }
        }
        __syncthreads();
    }

#pragma unroll
    for (int mt = 0; mt < 2; mt++)
#pragma unroll
        for (int nt = 0; nt < 4; nt++) {
            const int col = n0 + wn * 32 + nt * 8 + ((lane & 3) << 1);
            const float bx = bias[col], by = bias[col + 1];
            const int r0 = m0 + wm * 32 + mt * 16 + (lane >> 2);
            float o0 = acc[mt][nt][0] + bx, o1 = acc[mt][nt][1] + by;
            float o2 = acc[mt][nt][2] + bx, o3 = acc[mt][nt][3] + by;
            if (relu) {
                o0 = fmaxf(o0, 0.f); o1 = fmaxf(o1, 0.f);
                o2 = fmaxf(o2, 0.f); o3 = fmaxf(o3, 0.f);
            }
            if (r0 < M)     { float2 v = make_float2(o0, o1); *(float2*)(C + (size_t)r0 * N + col) = v; }
            if (r0 + 8 < M) { float2 v = make_float2(o2, o3); *(float2*)(C + (size_t)(r0 + 8) * N + col) = v; }
        }
}

/* ------------------------------------------------------------------ */
/* fused: ex[e] = exp(dot(q[dst],k[src])*scale); denom[dst] += ex      */
/* (no max subtraction: |score| < 0.1, softmax identical)              */
/* ------------------------------------------------------------------ */
__global__ void edge_score_exp(const float* __restrict__ qkvs,
                               const int* __restrict__ src, const int* __restrict__ dst,
                               float* __restrict__ ex, float* __restrict__ denom) {
    int e = (blockIdx.x * blockDim.x + threadIdx.x) >> 5;
    int lane = threadIdx.x & 31;
    if (e >= N_TX) return;
    int dd = dst[e], ss = src[e];
    float4 qv = ((const float4*)(qkvs + (size_t)dd * QLD))[lane];
    float4 kv = ((const float4*)(qkvs + (size_t)ss * QLD + 128))[lane];
    float acc = qv.x * kv.x + qv.y * kv.y + qv.z * kv.z + qv.w * kv.w;
#pragma unroll
    for (int o = 16; o; o >>= 1) acc += __shfl_xor_sync(0xFFFFFFFFu, acc, o);
    if (lane == 0) {
        float v = expf(acc * SCALE);
        ex[e] = v;
        atomicAdd(&denom[dd], v);
    }
}

__global__ void edge_agg(const float* __restrict__ ex, const float* __restrict__ denom,
                         const int* __restrict__ src, const int* __restrict__ dst,
                         float* __restrict__ qkvs) {
    int e = (blockIdx.x * blockDim.x + threadIdx.x) >> 5;
    int lane = threadIdx.x & 31;
    if (e >= N_TX) return;
    int dd = dst[e], ss = src[e];
    float alpha = ex[e] / denom[dd];
    float4 vv = ((const float4*)(qkvs + (size_t)ss * QLD + 256))[lane];
    float* o = qkvs + (size_t)dd * QLD + 384 + (lane << 2);
    atomicAdd(o + 0, alpha * vv.x);
    atomicAdd(o + 1, alpha * vv.y);
    atomicAdd(o + 2, alpha * vv.z);
    atomicAdd(o + 3, alpha * vv.w);
}

__global__ void layernorm(const float* __restrict__ qkvs,
                          const float* __restrict__ g, const float* __restrict__ b,
                          float* __restrict__ hn) {
    int r = (blockIdx.x * blockDim.x + threadIdx.x) >> 5;
    int lane = threadIdx.x & 31;
    if (r >= N_ENT) return;
    float4 x = ((const float4*)(qkvs + (size_t)r * QLD + 384))[lane];
    float s = x.x + x.y + x.z + x.w;
#pragma unroll
    for (int o = 16; o; o >>= 1) s += __shfl_xor_sync(0xFFFFFFFFu, s, o);
    float mu = s * (1.f / 128.f);
    float dx = x.x - mu, dy = x.y - mu, dz = x.z - mu, dw = x.w - mu;
    float v = dx * dx + dy * dy + dz * dz + dw * dw;
#pragma unroll
    for (int o = 16; o; o >>= 1) v += __shfl_xor_sync(0xFFFFFFFFu, v, o);
    float rstd = rsqrtf(v * (1.f / 128.f) + EPS);
    float4 gg = ((const float4*)g)[lane];
    float4 bb = ((const float4*)b)[lane];
    float4 o4;
    o4.x = dx * rstd * gg.x + bb.x;
    o4.y = dy * rstd * gg.y + bb.y;
    o4.z = dz * rstd * gg.z + bb.z;
    o4.w = dw * rstd * gg.w + bb.w;
    ((float4*)(hn + (size_t)r * D))[lane] = o4;
}

__global__ void scatter_add(const float* __restrict__ hn,
                            const int* __restrict__ src, const int* __restrict__ dst,
                            float* __restrict__ comb, int colofs) {
    int e = (blockIdx.x * blockDim.x + threadIdx.x) >> 5;
    int lane = threadIdx.x & 31;
    if (e >= N_TX) return;
    float4 hv = ((const float4*)(hn + (size_t)src[e] * D))[lane];
    float* c = comb + (size_t)dst[e] * CDIM + colofs + (lane << 2);
    atomicAdd(c + 0, hv.x);
    atomicAdd(c + 1, hv.y);
    atomicAdd(c + 2, hv.z);
    atomicAdd(c + 3, hv.w);
}

__global__ void final_dot(const float* __restrict__ x2, const float* __restrict__ W3,
                          const float* __restrict__ b3, float* __restrict__ out) {
    int r = (blockIdx.x * blockDim.x + threadIdx.x) >> 5;
    int lane = threadIdx.x & 31;
    if (r >= N_TX) return;
    float2 xv = ((const float2*)(x2 + (size_t)r * 64))[lane];
    float2 wv = ((const float2*)W3)[lane];
    float s = xv.x * wv.x + xv.y * wv.y;
#pragma unroll
    for (int o = 16; o; o >>= 1) s += __shfl_xor_sync(0xFFFFFFFFu, s, o);
    if (lane == 0) out[r] = s + b3[0];
}

/* ------------------------------------------------------------------ */
extern "C" void kernel_launch(void* const* d_in, const int* in_sizes, int n_in,
                              void* d_out, int out_size) {
    const float* tx_x  = (const float*)d_in[0];
    const int*   ent_x = (const int*)d_in[1];
    const int*   e_src = (const int*)d_in[2];
    const int*   e_dst = (const int*)d_in[3];
    const float* emb   = (const float*)d_in[4];
    const float* ln_g  = (const float*)d_in[5];
    const float* ln_b  = (const float*)d_in[6];
    const float* Wq = (const float*)d_in[7];  const float* bq = (const float*)d_in[8];
    const float* Wk = (const float*)d_in[9];  const float* bk = (const float*)d_in[10];
    const float* Wv = (const float*)d_in[11]; const float* bv = (const float*)d_in[12];
    const float* Ws = (const float*)d_in[13]; const float* bs = (const float*)d_in[14];
    const float* W1 = (const float*)d_in[15]; const float* b1 = (const float*)d_in[16];
    const float* W2 = (const float*)d_in[17]; const float* b2 = (const float*)d_in[18];
    const float* W3 = (const float*)d_in[19]; const float* b3 = (const float*)d_in[20];
    float* out = (float*)d_out;

    float *qkvs, *hn, *ex, *denom, *comb, *x1, *x2, *Bcat, *bcat;
    __nv_bfloat16 *Ah, *Al, *Bh, *Bl, *W1h, *W1l, *W2h, *W2l;
    cudaGetSymbolAddress((void**)&qkvs,  g_qkvs);
    cudaGetSymbolAddress((void**)&hn,    g_hn);
    cudaGetSymbolAddress((void**)&ex,    g_ex);
    cudaGetSymbolAddress((void**)&denom, g_denom);
    cudaGetSymbolAddress((void**)&comb,  g_comb);
    cudaGetSymbolAddress((void**)&x1,    g_x1);
    cudaGetSymbolAddress((void**)&x2,    g_x2);
    cudaGetSymbolAddress((void**)&Bcat,  g_Bcat);
    cudaGetSymbolAddress((void**)&bcat,  g_bcat);
    cudaGetSymbolAddress((void**)&Ah,    g_Ah);
    cudaGetSymbolAddress((void**)&Al,    g_Al);
    cudaGetSymbolAddress((void**)&Bh,    g_Bh);
    cudaGetSymbolAddress((void**)&Bl,    g_Bl);
    cudaGetSymbolAddress((void**)&W1h,   g_W1h);
    cudaGetSymbolAddress((void**)&W1l,   g_W1l);
    cudaGetSymbolAddress((void**)&W2h,   g_W2h);
    cudaGetSymbolAddress((void**)&W2l,   g_W2l);

    pack_w<<<(D * QLD + 255) / 256, 256>>>(Wq, Wk, Wv, Ws, bq, bk, bv, bs, Bcat, bcat);
    split_w<<<(D * QLD + 255) / 256, 256>>>(Bcat, Bh, Bl, D, D, QLD);
    split_w<<<(K1PAD * D + 255) / 256, 256>>>(W1, W1h, W1l, CDIM, K1PAD, D);
    split_w<<<(D * 64 + 255) / 256, 256>>>(W2, W2h, W2l, D, D, 64);
    comb_init<<<(N_TX * (CDIM / 4) + 255) / 256, 256>>>(tx_x, comb);

    for (int t = 0; t < T; t++) {
        const int* idx = ent_x + (size_t)t * N_ENT;
        const int* src = e_src + (size_t)t * N_TX;
        const int* dst = e_dst + (size_t)t * N_TX;
        const float* embt = emb + (size_t)t * N_ENT * D;

        gather_split<<<(N_ENT * (D / 4) + 255) / 256, 256>>>(embt, idx, Ah, Al);
        init_d<<<(N_ENT + 255) / 256, 256>>>(denom);
        gemm128<1><<<dim3(QLD / 128, MPAD_E / 128), 256>>>(
            NULL, Ah, Al, Bh, Bl, bcat, qkvs, N_ENT, QLD, D, D, 0);
        edge_score_exp<<<(N_TX * 32 + 255) / 256, 256>>>(qkvs, src, dst, ex, denom);
        edge_agg<<<(N_TX * 32 + 255) / 256, 256>>>(ex, denom, src, dst, qkvs);
        layernorm<<<(N_ENT * 32 + 255) / 256, 256>>>(qkvs, ln_g + t * D, ln_b + t * D, hn);
        scatter_add<<<(N_TX * 32 + 255) / 256, 256>>>(hn, src, dst, comb, F + t * D);
    }

    /* classifier */
    gemm128<0><<<dim3(1, MPAD_T / 128), 256>>>(
        comb, NULL, NULL, W1h, W1l, b1, x1, N_TX, D, CDIM, K1PAD, 1);
    gemm_bf16x2<<<dim3(1, (N_TX + 127) / 128), 256>>>(
        x1, W2h, W2l, b2, x2, N_TX, 64, D, D, 1);
    final_dot<<<(N_TX * 32 + 255) / 256, 256>>>(x2, W3, b3, out);
}

// round 5
// speedup vs baseline: 1.7748x; 1.1331x over previous
#include <cuda_runtime.h>
#include <cuda_bf16.h>
#include <math.h>
#include <stdint.h>
#include <stddef.h>

#define N_ENT 50000
#define N_TX  40000
#define D     128
#define F     432
#define T     11
#define CDIM  (F + T * D)      /* 1840 */
#define K1PAD 1856
#define QLD   512
#define EPS   1e-5f
#define SCALE 0.08838834764831845f

#define MPAD_E 50048           /* 391*128 */
#define MPAD_T 40064           /* 313*128 */

/* ------------------------------------------------------------------ */
/* Scratch: per-type batched buffers                                   */
/* ------------------------------------------------------------------ */
__device__ float    g_qkvs[(size_t)T * N_ENT * QLD];   /* 1.13 GB */
__device__ float    g_S[(size_t)T * N_ENT * D];        /* 282 MB unnormalized agg */
__device__ float    g_denom[(size_t)T * N_ENT];
__device__ float    g_comb[(size_t)MPAD_T * CDIM];     /* rows >= N_TX stay 0 */
__device__ float    g_x1[(size_t)N_TX * D];
__device__ float    g_x2[(size_t)N_TX * 64];
__device__ float    g_Bcat[D * QLD];
__device__ float    g_bcat[QLD];
__device__ __nv_bfloat16 g_Ah[(size_t)T * MPAD_E * D], g_Al[(size_t)T * MPAD_E * D];
__device__ __nv_bfloat16 g_Bh[D * QLD],    g_Bl[D * QLD];
__device__ __nv_bfloat16 g_W1h[K1PAD * D], g_W1l[K1PAD * D];
__device__ __nv_bfloat16 g_W2h[D * 64],    g_W2l[D * 64];

/* ------------------------------------------------------------------ */
__global__ void pack_w(const float* __restrict__ Wq, const float* __restrict__ Wk,
                       const float* __restrict__ Wv, const float* __restrict__ Ws,
                       const float* __restrict__ bq, const float* __restrict__ bk,
                       const float* __restrict__ bv, const float* __restrict__ bs,
                       float* __restrict__ Bcat, float* __restrict__ bcat) {
    int i = blockIdx.x * blockDim.x + threadIdx.x;
    if (i >= D * QLD) return;
    int n = i & (QLD - 1);
    int k = i >> 9;
    const float* W = (n < 128) ? Wq : (n < 256) ? Wk : (n < 384) ? Wv : Ws;
    int nn = n & 127;
    Bcat[k * QLD + n] = W[k * 128 + nn];
    if (k == 0) {
        const float* bb = (n < 128) ? bq : (n < 256) ? bk : (n < 384) ? bv : bs;
        bcat[n] = bb[nn];
    }
}

__global__ void split_w(const float* __restrict__ src,
                        __nv_bfloat16* __restrict__ dh, __nv_bfloat16* __restrict__ dl,
                        int Kreal, int Kpad, int Ncols) {
    int i = blockIdx.x * blockDim.x + threadIdx.x;
    if (i >= Kpad * Ncols) return;
    int k = i / Ncols;
    float v = (k < Kreal) ? src[i] : 0.f;
    __nv_bfloat16 h = __float2bfloat16_rn(v);
    __nv_bfloat16 l = __float2bfloat16_rn(v - __bfloat162float(h));
    dh[i] = h;
    dl[i] = l;
}

/* all types: gather emb rows by idx, split bf16 hi/lo                 */
__global__ void gather_split_all(const float* __restrict__ emb, const int* __restrict__ ent_x,
                                 __nv_bfloat16* __restrict__ Ah, __nv_bfloat16* __restrict__ Al) {
    long long i = (long long)blockIdx.x * blockDim.x + threadIdx.x;
    const long long TOT = (long long)T * N_ENT * (D / 4);
    if (i >= TOT) return;
    int c4  = (int)(i & 31);
    long long rowg = i >> 5;               /* t*N_ENT + row */
    int t   = (int)(rowg / N_ENT);
    int row = (int)(rowg - (long long)t * N_ENT);
    int r = ent_x[rowg];
    float4 v = ((const float4*)(emb + ((size_t)t * N_ENT + r) * D))[c4];
    float vv[4] = { v.x, v.y, v.z, v.w };
    __nv_bfloat16 h[4], l[4];
#pragma unroll
    for (int j = 0; j < 4; j++) {
        h[j] = __float2bfloat16_rn(vv[j]);
        l[j] = __float2bfloat16_rn(vv[j] - __bfloat162float(h[j]));
    }
    size_t o = ((size_t)t * MPAD_E + row) * D + (c4 << 2);
    *(uint2*)(Ah + o) = *(uint2*)h;
    *(uint2*)(Al + o) = *(uint2*)l;
}

__global__ void comb_init(const float* __restrict__ tx, float* __restrict__ comb) {
    int i = blockIdx.x * blockDim.x + threadIdx.x;
    const int TOT = N_TX * (CDIM / 4);
    if (i >= TOT) return;
    int row = i / (CDIM / 4);
    int c4  = i - row * (CDIM / 4);
    float4 v = make_float4(0.f, 0.f, 0.f, 0.f);
    if (c4 < F / 4) v = ((const float4*)(tx + (size_t)row * F))[c4];
    ((float4*)(comb + (size_t)row * CDIM))[c4] = v;
}

/* zero S (T*N_ENT*D floats) and denom (T*N_ENT floats)                */
__global__ void zero_sd(float* __restrict__ S, float* __restrict__ denom) {
    long long i = (long long)blockIdx.x * blockDim.x + threadIdx.x;
    const long long S4 = (long long)T * N_ENT * D / 4;
    if (i < S4) ((float4*)S)[i] = make_float4(0.f, 0.f, 0.f, 0.f);
    if (i < (long long)T * N_ENT) denom[i] = 0.f;
}

/* ------------------------------------------------------------------ */
__device__ __forceinline__ void ldsm4(uint32_t* r, const void* p) {
    uint32_t a = (uint32_t)__cvta_generic_to_shared(p);
    asm volatile("ldmatrix.sync.aligned.m8n8.x4.shared.b16 {%0,%1,%2,%3}, [%4];"
                 : "=r"(r[0]), "=r"(r[1]), "=r"(r[2]), "=r"(r[3]) : "r"(a));
}
__device__ __forceinline__ void ldsm4t(uint32_t* r, const void* p) {
    uint32_t a = (uint32_t)__cvta_generic_to_shared(p);
    asm volatile("ldmatrix.sync.aligned.m8n8.x4.trans.shared.b16 {%0,%1,%2,%3}, [%4];"
                 : "=r"(r[0]), "=r"(r[1]), "=r"(r[2]), "=r"(r[3]) : "r"(a));
}
__device__ __forceinline__ void mma16816(float* c, const uint32_t* a, const uint32_t* b) {
    asm volatile(
        "mma.sync.aligned.m16n8k16.row.col.f32.bf16.bf16.f32 "
        "{%0,%1,%2,%3}, {%4,%5,%6,%7}, {%8,%9}, {%0,%1,%2,%3};\n"
        : "+f"(c[0]), "+f"(c[1]), "+f"(c[2]), "+f"(c[3])
        : "r"(a[0]), "r"(a[1]), "r"(a[2]), "r"(a[3]), "r"(b[0]), "r"(b[1]));
}

/* ------------------------------------------------------------------ */
/* gemm128 batched: per-z slice C = A @ B + bias. BM=BN=128 BK=32.     */
/* SPLITA=1: A pre-split bf16 (padded rows, no guards), strides in z.  */
/* SPLITA=0: A fp32 padded rows, split on the fly (classifier).        */
/* ------------------------------------------------------------------ */
#define ASTR  40
#define BSTR2 144

template<int SPLITA>
__global__ void __launch_bounds__(256) gemm128(
    const float* __restrict__ Afp,
    const __nv_bfloat16* __restrict__ Ahg, const __nv_bfloat16* __restrict__ Alg,
    const __nv_bfloat16* __restrict__ Bhg, const __nv_bfloat16* __restrict__ Blg,
    const float* __restrict__ bias, float* __restrict__ C,
    int M, int N, int Kreal, int Kpad, int relu,
    long long strideA, long long strideC)
{
    __shared__ __nv_bfloat16 Ahs[128][ASTR];
    __shared__ __nv_bfloat16 Als[128][ASTR];
    __shared__ __nv_bfloat16 Bhs[32][BSTR2];
    __shared__ __nv_bfloat16 Bls[32][BSTR2];

    const int tid  = threadIdx.x;
    const int lane = tid & 31;
    const int warp = tid >> 5;
    const int wm   = warp >> 1;
    const int wn   = warp & 1;
    const int m0   = blockIdx.y * 128;
    const int n0   = blockIdx.x * 128;
    const long long zA = (long long)blockIdx.z * strideA;
    const long long zC = (long long)blockIdx.z * strideC;

    const int arow  = tid >> 1;
    const int acolg = (tid & 1) << 4;
    const int brow  = tid >> 3;
    const int bcol  = (tid & 7) << 4;

    float acc[2][8][4];
#pragma unroll
    for (int a = 0; a < 2; a++)
#pragma unroll
        for (int b = 0; b < 8; b++)
#pragma unroll
            for (int c = 0; c < 4; c++) acc[a][b][c] = 0.f;

    uint4  sAh[2], sAl[2];
    float4 sAf[4];
    uint4  sBh[2], sBl[2];

#define LOADT(K0)                                                              \
    do {                                                                       \
        if (SPLITA) {                                                          \
            size_t ao = (size_t)(zA + (long long)(m0 + arow) * Kreal           \
                                 + (K0) + acolg);                              \
            sAh[0] = *(const uint4*)(Ahg + ao);                                \
            sAh[1] = *(const uint4*)(Ahg + ao + 8);                            \
            sAl[0] = *(const uint4*)(Alg + ao);                                \
            sAl[1] = *(const uint4*)(Alg + ao + 8);                            \
        } else {                                                               \
            if ((K0) + acolg < Kreal) {                                        \
                const float4* p = (const float4*)(Afp +                        \
                    (size_t)(m0 + arow) * Kreal + (K0) + acolg);               \
                sAf[0] = p[0]; sAf[1] = p[1]; sAf[2] = p[2]; sAf[3] = p[3];    \
            } else {                                                           \
                sAf[0] = sAf[1] = sAf[2] = sAf[3] =                            \
                    make_float4(0.f, 0.f, 0.f, 0.f);                           \
            }                                                                  \
        }                                                                      \
        size_t bo = (size_t)((K0) + brow) * N + n0 + bcol;                     \
        sBh[0] = *(const uint4*)(Bhg + bo);                                    \
        sBh[1] = *(const uint4*)(Bhg + bo + 8);                                \
        sBl[0] = *(const uint4*)(Blg + bo);                                    \
        sBl[1] = *(const uint4*)(Blg + bo + 8);                                \
    } while (0)

    LOADT(0);

    for (int k0 = 0; k0 < Kpad; k0 += 32) {
        if (SPLITA) {
            *(uint4*)&Ahs[arow][acolg]     = sAh[0];
            *(uint4*)&Ahs[arow][acolg + 8] = sAh[1];
            *(uint4*)&Als[arow][acolg]     = sAl[0];
            *(uint4*)&Als[arow][acolg + 8] = sAl[1];
        } else {
            const float* fv = (const float*)sAf;
#pragma unroll
            for (int j = 0; j < 8; j++) {
                float x0 = fv[2 * j], x1 = fv[2 * j + 1];
                __nv_bfloat16 h0 = __float2bfloat16_rn(x0);
                __nv_bfloat16 l0 = __float2bfloat16_rn(x0 - __bfloat162float(h0));
                __nv_bfloat16 h1 = __float2bfloat16_rn(x1);
                __nv_bfloat16 l1 = __float2bfloat16_rn(x1 - __bfloat162float(h1));
                __nv_bfloat162 hp; hp.x = h0; hp.y = h1;
                __nv_bfloat162 lp; lp.x = l0; lp.y = l1;
                *(__nv_bfloat162*)&Ahs[arow][acolg + 2 * j] = hp;
                *(__nv_bfloat162*)&Als[arow][acolg + 2 * j] = lp;
            }
        }
        *(uint4*)&Bhs[brow][bcol]     = sBh[0];
        *(uint4*)&Bhs[brow][bcol + 8] = sBh[1];
        *(uint4*)&Bls[brow][bcol]     = sBl[0];
        *(uint4*)&Bls[brow][bcol + 8] = sBl[1];
        __syncthreads();

        int kn = k0 + 32;
        if (kn < Kpad) LOADT(kn);

#pragma unroll
        for (int ks = 0; ks < 2; ks++) {
            const int kk = ks << 4;
            uint32_t afh[2][4], afl[2][4];
#pragma unroll
            for (int mt = 0; mt < 2; mt++) {
                const int r = wm * 32 + mt * 16 + (lane & 15);
                const int c = kk + ((lane >> 4) << 3);
                ldsm4(afh[mt], &Ahs[r][c]);
                ldsm4(afl[mt], &Als[r][c]);
            }
            uint32_t bfh[4][4], bfl[4][4];
#pragma unroll
            for (int nc = 0; nc < 4; nc++) {
                const int r = kk + (lane & 15);
                const int c = wn * 64 + nc * 16 + ((lane >> 4) << 3);
                ldsm4t(bfh[nc], &Bhs[r][c]);
                ldsm4t(bfl[nc], &Bls[r][c]);
            }
#pragma unroll
            for (int mt = 0; mt < 2; mt++)
#pragma unroll
                for (int nt = 0; nt < 8; nt++) {
                    const int nc = nt >> 1, p = (nt & 1) << 1;
                    uint32_t bh2[2] = { bfh[nc][p], bfh[nc][p + 1] };
                    uint32_t bl2[2] = { bfl[nc][p], bfl[nc][p + 1] };
                    mma16816(acc[mt][nt], afh[mt], bh2);
                    mma16816(acc[mt][nt], afl[mt], bh2);
                    mma16816(acc[mt][nt], afh[mt], bl2);
                }
        }
        __syncthreads();
    }
#undef LOADT

#pragma unroll
    for (int mt = 0; mt < 2; mt++)
#pragma unroll
        for (int nt = 0; nt < 8; nt++) {
            const int col = n0 + wn * 64 + nt * 8 + ((lane & 3) << 1);
            const float bx = bias[col], by = bias[col + 1];
            const int r0 = m0 + wm * 32 + mt * 16 + (lane >> 2);
            float o0 = acc[mt][nt][0] + bx, o1 = acc[mt][nt][1] + by;
            float o2 = acc[mt][nt][2] + bx, o3 = acc[mt][nt][3] + by;
            if (relu) {
                o0 = fmaxf(o0, 0.f); o1 = fmaxf(o1, 0.f);
                o2 = fmaxf(o2, 0.f); o3 = fmaxf(o3, 0.f);
            }
            if (r0 < M)     { float2 v = make_float2(o0, o1);
                              *(float2*)(C + zC + (size_t)r0 * N + col) = v; }
            if (r0 + 8 < M) { float2 v = make_float2(o2, o3);
                              *(float2*)(C + zC + (size_t)(r0 + 8) * N + col) = v; }
        }
}

/* ------------------------------------------------------------------ */
/* BN=64 GEMM for the small classifier GEMM2 (N=64)                    */
/* ------------------------------------------------------------------ */
#define BSTR 72
__global__ void __launch_bounds__(256) gemm_bf16x2(
    const float* __restrict__ A,
    const __nv_bfloat16* __restrict__ Bhg, const __nv_bfloat16* __restrict__ Blg,
    const float* __restrict__ bias, float* __restrict__ C,
    int M, int N, int Kreal, int Kpad, int relu)
{
    __shared__ __nv_bfloat16 Ah[128][ASTR];
    __shared__ __nv_bfloat16 Al[128][ASTR];
    __shared__ __nv_bfloat16 Bhs[32][BSTR];
    __shared__ __nv_bfloat16 Bls[32][BSTR];

    const int tid  = threadIdx.x;
    const int lane = tid & 31;
    const int warp = tid >> 5;
    const int wm   = warp >> 1;
    const int wn   = warp & 1;
    const int m0   = blockIdx.y * 128;
    const int n0   = blockIdx.x * 64;

    const int arow  = tid >> 1;
    const int acolg = (tid & 1) << 4;
    const float* aptr = NULL;
    {
        int gm = m0 + arow;
        if (gm < M) aptr = A + (size_t)gm * Kreal;
    }
    const int brow  = tid >> 3;
    const int bcolg = (tid & 7) << 3;

    float acc[2][4][4];
#pragma unroll
    for (int i = 0; i < 2; i++)
#pragma unroll
        for (int j = 0; j < 4; j++)
#pragma unroll
            for (int l = 0; l < 4; l++) acc[i][j][l] = 0.f;

    for (int k0 = 0; k0 < Kpad; k0 += 32) {
        float4 f[4];
        if (aptr && (k0 + acolg) < Kreal) {
            const float4* p = (const float4*)(aptr + k0 + acolg);
            f[0] = p[0]; f[1] = p[1]; f[2] = p[2]; f[3] = p[3];
        } else {
            f[0] = f[1] = f[2] = f[3] = make_float4(0.f, 0.f, 0.f, 0.f);
        }
        const float* fv = (const float*)f;
#pragma unroll
        for (int j = 0; j < 8; j++) {
            float x0 = fv[2 * j], x1 = fv[2 * j + 1];
            __nv_bfloat16 h0 = __float2bfloat16_rn(x0);
            __nv_bfloat16 l0 = __float2bfloat16_rn(x0 - __bfloat162float(h0));
            __nv_bfloat16 h1 = __float2bfloat16_rn(x1);
            __nv_bfloat16 l1 = __float2bfloat16_rn(x1 - __bfloat162float(h1));
            __nv_bfloat162 hp; hp.x = h0; hp.y = h1;
            __nv_bfloat162 lp; lp.x = l0; lp.y = l1;
            *(__nv_bfloat162*)&Ah[arow][acolg + 2 * j] = hp;
            *(__nv_bfloat162*)&Al[arow][acolg + 2 * j] = lp;
        }
        {
            size_t off = (size_t)(k0 + brow) * N + n0 + bcolg;
            uint4 vh = *(const uint4*)(Bhg + off);
            uint4 vl = *(const uint4*)(Blg + off);
            *(uint4*)&Bhs[brow][bcolg] = vh;
            *(uint4*)&Bls[brow][bcolg] = vl;
        }
        __syncthreads();

#pragma unroll
        for (int ks = 0; ks < 2; ks++) {
            const int kk = ks << 4;
            uint32_t afh[2][4], afl[2][4];
#pragma unroll
            for (int mt = 0; mt < 2; mt++) {
                const int r = wm * 32 + mt * 16 + (lane & 15);
                const int c = kk + ((lane >> 4) << 3);
                ldsm4(afh[mt], &Ah[r][c]);
                ldsm4(afl[mt], &Al[r][c]);
            }
            uint32_t bfh[2][4], bfl[2][4];
#pragma unroll
            for (int nc = 0; nc < 2; nc++) {
                const int r = kk + (lane & 15);
                const int c = wn * 32 + nc * 16 + ((lane >> 4) << 3);
                ldsm4t(bfh[nc], &Bhs[r][c]);
                ldsm4t(bfl[nc], &Bls[r][c]);
            }
#pragma unroll
            for (int mt = 0; mt < 2; mt++)
#pragma unroll
                for (int nt = 0; nt < 4; nt++) {
                    const int nc = nt >> 1, p = (nt & 1) << 1;
                    uint32_t bh2[2] = { bfh[nc][p], bfh[nc][p + 1] };
                    uint32_t bl2[2] = { bfl[nc][p], bfl[nc][p + 1] };
                    mma16816(acc[mt][nt], afh[mt], bh2);
                    mma16816(acc[mt][nt], afl[mt], bh2);
                    mma16816(acc[mt][nt], afh[mt], bl2);
                }
        }
        __syncthreads();
    }

#pragma unroll
    for (int mt = 0; mt < 2; mt++)
#pragma unroll
        for (int nt = 0; nt < 4; nt++) {
            const int col = n0 + wn * 32 + nt * 8 + ((lane & 3) << 1);
            const float bx = bias[col], by = bias[col + 1];
            const int r0 = m0 + wm * 32 + mt * 16 + (lane >> 2);
            float o0 = acc[mt][nt][0] + bx, o1 = acc[mt][nt][1] + by;
            float o2 = acc[mt][nt][2] + bx, o3 = acc[mt][nt][3] + by;
            if (relu) {
                o0 = fmaxf(o0, 0.f); o1 = fmaxf(o1, 0.f);
                o2 = fmaxf(o2, 0.f); o3 = fmaxf(o3, 0.f);
            }
            if (r0 < M)     { float2 v = make_float2(o0, o1); *(float2*)(C + (size_t)r0 * N + col) = v; }
            if (r0 + 8 < M) { float2 v = make_float2(o2, o3); *(float2*)(C + (size_t)(r0 + 8) * N + col) = v; }
        }
}

/* ------------------------------------------------------------------ */
/* Fused edge pass (all types): ex = exp(dot(q[dst],k[src])*scale);    */
/* denom[dst] += ex; S[dst] += ex * v[src]   (deferred normalization)  */
/* ------------------------------------------------------------------ */
__global__ void edge_fused_all(const float* __restrict__ qkvs,
                               const int* __restrict__ e_src, const int* __restrict__ e_dst,
                               float* __restrict__ S, float* __restrict__ denom) {
    long long w = ((long long)blockIdx.x * blockDim.x + threadIdx.x) >> 5;
    int lane = threadIdx.x & 31;
    if (w >= (long long)T * N_TX) return;
    int t = (int)(w / N_TX);
    int e = (int)(w - (long long)t * N_TX);
    int dd = e_dst[(size_t)t * N_TX + e];
    int ss = e_src[(size_t)t * N_TX + e];
    const float* qk = qkvs + (size_t)t * N_ENT * QLD;
    float4 qv = ((const float4*)(qk + (size_t)dd * QLD))[lane];
    float4 kv = ((const float4*)(qk + (size_t)ss * QLD + 128))[lane];
    float acc = qv.x * kv.x + qv.y * kv.y + qv.z * kv.z + qv.w * kv.w;
#pragma unroll
    for (int o = 16; o; o >>= 1) acc += __shfl_xor_sync(0xFFFFFFFFu, acc, o);
    float exv = expf(acc * SCALE);   /* |score|<<1: no max-shift needed */
    float4 vv = ((const float4*)(qk + (size_t)ss * QLD + 256))[lane];
    float* so = S + ((size_t)t * N_ENT + dd) * D + (lane << 2);
    atomicAdd(so + 0, exv * vv.x);
    atomicAdd(so + 1, exv * vv.y);
    atomicAdd(so + 2, exv * vv.z);
    atomicAdd(so + 3, exv * vv.w);
    if (lane == 0) atomicAdd(&denom[(size_t)t * N_ENT + dd], exv);
}

/* ------------------------------------------------------------------ */
/* Fused LN + scatter (all types), per edge:                           */
/* out = skip[src] + S[src]/denom[src]; LN(out); comb[dst] += ln       */
/* ------------------------------------------------------------------ */
__global__ void ln_scatter_all(const float* __restrict__ qkvs,
                               const float* __restrict__ S, const float* __restrict__ denom,
                               const int* __restrict__ e_src, const int* __restrict__ e_dst,
                               const float* __restrict__ ln_g, const float* __restrict__ ln_b,
                               float* __restrict__ comb) {
    long long w = ((long long)blockIdx.x * blockDim.x + threadIdx.x) >> 5;
    int lane = threadIdx.x & 31;
    if (w >= (long long)T * N_TX) return;
    int t = (int)(w / N_TX);
    int e = (int)(w - (long long)t * N_TX);
    int ss = e_src[(size_t)t * N_TX + e];
    int dd = e_dst[(size_t)t * N_TX + e];

    float4 skip = ((const float4*)(qkvs + ((size_t)t * N_ENT + ss) * QLD + 384))[lane];
    float dn = denom[(size_t)t * N_ENT + ss];
    float inv = (dn > 0.f) ? (1.f / dn) : 0.f;
    float4 sv = ((const float4*)(S + ((size_t)t * N_ENT + ss) * D))[lane];
    float x0 = skip.x + sv.x * inv;
    float x1 = skip.y + sv.y * inv;
    float x2 = skip.z + sv.z * inv;
    float x3 = skip.w + sv.w * inv;

    float s = x0 + x1 + x2 + x3;
#pragma unroll
    for (int o = 16; o; o >>= 1) s += __shfl_xor_sync(0xFFFFFFFFu, s, o);
    float mu = s * (1.f / 128.f);
    float d0 = x0 - mu, d1 = x1 - mu, d2 = x2 - mu, d3 = x3 - mu;
    float v = d0 * d0 + d1 * d1 + d2 * d2 + d3 * d3;
#pragma unroll
    for (int o = 16; o; o >>= 1) v += __shfl_xor_sync(0xFFFFFFFFu, v, o);
    float rstd = rsqrtf(v * (1.f / 128.f) + EPS);

    float4 gg = ((const float4*)(ln_g + t * D))[lane];
    float4 bb = ((const float4*)(ln_b + t * D))[lane];
    float* c = comb + (size_t)dd * CDIM + F + t * D + (lane << 2);
    atomicAdd(c + 0, d0 * rstd * gg.x + bb.x);
    atomicAdd(c + 1, d1 * rstd * gg.y + bb.y);
    atomicAdd(c + 2, d2 * rstd * gg.z + bb.z);
    atomicAdd(c + 3, d3 * rstd * gg.w + bb.w);
}

__global__ void final_dot(const float* __restrict__ x2, const float* __restrict__ W3,
                          const float* __restrict__ b3, float* __restrict__ out) {
    int r = (blockIdx.x * blockDim.x + threadIdx.x) >> 5;
    int lane = threadIdx.x & 31;
    if (r >= N_TX) return;
    float2 xv = ((const float2*)(x2 + (size_t)r * 64))[lane];
    float2 wv = ((const float2*)W3)[lane];
    float s = xv.x * wv.x + xv.y * wv.y;
#pragma unroll
    for (int o = 16; o; o >>= 1) s += __shfl_xor_sync(0xFFFFFFFFu, s, o);
    if (lane == 0) out[r] = s + b3[0];
}

/* ------------------------------------------------------------------ */
extern "C" void kernel_launch(void* const* d_in, const int* in_sizes, int n_in,
                              void* d_out, int out_size) {
    const float* tx_x  = (const float*)d_in[0];
    const int*   ent_x = (const int*)d_in[1];
    const int*   e_src = (const int*)d_in[2];
    const int*   e_dst = (const int*)d_in[3];
    const float* emb   = (const float*)d_in[4];
    const float* ln_g  = (const float*)d_in[5];
    const float* ln_b  = (const float*)d_in[6];
    const float* Wq = (const float*)d_in[7];  const float* bq = (const float*)d_in[8];
    const float* Wk = (const float*)d_in[9];  const float* bk = (const float*)d_in[10];
    const float* Wv = (const float*)d_in[11]; const float* bv = (const float*)d_in[12];
    const float* Ws = (const float*)d_in[13]; const float* bs = (const float*)d_in[14];
    const float* W1 = (const float*)d_in[15]; const float* b1 = (const float*)d_in[16];
    const float* W2 = (const float*)d_in[17]; const float* b2 = (const float*)d_in[18];
    const float* W3 = (const float*)d_in[19]; const float* b3 = (const float*)d_in[20];
    float* out = (float*)d_out;

    float *qkvs, *S, *denom, *comb, *x1, *x2, *Bcat, *bcat;
    __nv_bfloat16 *Ah, *Al, *Bh, *Bl, *W1h, *W1l, *W2h, *W2l;
    cudaGetSymbolAddress((void**)&qkvs,  g_qkvs);
    cudaGetSymbolAddress((void**)&S,     g_S);
    cudaGetSymbolAddress((void**)&denom, g_denom);
    cudaGetSymbolAddress((void**)&comb,  g_comb);
    cudaGetSymbolAddress((void**)&x1,    g_x1);
    cudaGetSymbolAddress((void**)&x2,    g_x2);
    cudaGetSymbolAddress((void**)&Bcat,  g_Bcat);
    cudaGetSymbolAddress((void**)&bcat,  g_bcat);
    cudaGetSymbolAddress((void**)&Ah,    g_Ah);
    cudaGetSymbolAddress((void**)&Al,    g_Al);
    cudaGetSymbolAddress((void**)&Bh,    g_Bh);
    cudaGetSymbolAddress((void**)&Bl,    g_Bl);
    cudaGetSymbolAddress((void**)&W1h,   g_W1h);
    cudaGetSymbolAddress((void**)&W1l,   g_W1l);
    cudaGetSymbolAddress((void**)&W2h,   g_W2h);
    cudaGetSymbolAddress((void**)&W2l,   g_W2l);

    /* prologue */
    pack_w<<<(D * QLD + 255) / 256, 256>>>(Wq, Wk, Wv, Ws, bq, bk, bv, bs, Bcat, bcat);
    split_w<<<(D * QLD + 255) / 256, 256>>>(Bcat, Bh, Bl, D, D, QLD);
    split_w<<<(K1PAD * D + 255) / 256, 256>>>(W1, W1h, W1l, CDIM, K1PAD, D);
    split_w<<<(D * 64 + 255) / 256, 256>>>(W2, W2h, W2l, D, D, 64);
    comb_init<<<(N_TX * (CDIM / 4) + 255) / 256, 256>>>(tx_x, comb);
    zero_sd<<<(int)(((long long)T * N_ENT * D / 4 + 255) / 256), 256>>>(S, denom);
    gather_split_all<<<(int)(((long long)T * N_ENT * 32 + 255) / 256), 256>>>(emb, ent_x, Ah, Al);

    /* batched q|k|v|skip GEMM for all 11 types */
    gemm128<1><<<dim3(QLD / 128, MPAD_E / 128, T), 256>>>(
        NULL, Ah, Al, Bh, Bl, bcat, qkvs, N_ENT, QLD, D, D, 0,
        (long long)MPAD_E * D, (long long)N_ENT * QLD);

    /* batched edge passes */
    {
        long long nw = (long long)T * N_TX * 32;
        edge_fused_all<<<(int)((nw + 255) / 256), 256>>>(qkvs, e_src, e_dst, S, denom);
        ln_scatter_all<<<(int)((nw + 255) / 256), 256>>>(qkvs, S, denom, e_src, e_dst,
                                                         ln_g, ln_b, comb);
    }

    /* classifier */
    gemm128<0><<<dim3(1, MPAD_T / 128, 1), 256>>>(
        comb, NULL, NULL, W1h, W1l, b1, x1, N_TX, D, CDIM, K1PAD, 1, 0, 0);
    gemm_bf16x2<<<dim3(1, (N_TX + 127) / 128), 256>>>(
        x1, W2h, W2l, b2, x2, N_TX, 64, D, D, 1);
    final_dot<<<(N_TX * 32 + 255) / 256, 256>>>(x2, W3, b3, out);
}